// round 9
// baseline (speedup 1.0000x reference)
#include <cuda_runtime.h>
#include <cuda_bf16.h>
#include <cstdint>

// BasicLSTM via mma.sync (HMMA bf16, 3-term fp32-split emulation).
// SEQ=512, BATCH=64, HID=1024, LAYERS=2.
// R9: M=64 tiles, full-K per CTA (32 chunks), CTA-local cell -> ONE grid
// barrier per super-step, zero split-K global traffic. Parity-buffered h.

#define SEQ    512
#define BATCH  64
#define HID    1024
#define KTOT   2048
#define NOUT   4096
#define BH     (BATCH * HID)        // 65536
#define NBLK   128
#define NTHR   512
#define GTH    (NBLK * NTHR)
#define CHK    64                   // K per chunk
#define NCHK   (KTOT / CHK)         // 32
#define STGB   32768                // Ahi8K | Alo8K | Bhi8K | Blo8K
#define NSTG   3
#define DSMEM  (NSTG * STGB)        // 98304

// ---------------- device globals (no allocs) ----------------
__device__ __align__(128) __nv_bfloat16 g_xhi[(size_t)SEQ * HID * 64];
__device__ __align__(128) __nv_bfloat16 g_xlo[(size_t)SEQ * HID * 64];
__device__ __align__(128) __nv_bfloat16 g_wthi[(size_t)2 * NOUT * KTOT]; // [l][p][k]
__device__ __align__(128) __nv_bfloat16 g_wtlo[(size_t)2 * NOUT * KTOT];
__device__ __align__(128) __nv_bfloat16 g_hhi[4 * BH];    // [par*2+l][u][b]
__device__ __align__(128) __nv_bfloat16 g_hlo[4 * BH];
__device__ __align__(128) float g_c[2 * BH];              // [l][u][b]
__device__ __align__(128) float g_hf[2 * BH];             // [l][u][b]
__device__ unsigned g_bar_arrive;
__device__ unsigned g_bar_gen;

// ---------------- PTX helpers ----------------
__device__ __forceinline__ uint32_t smem_u32(const void* p) {
    uint32_t a;
    asm("{ .reg .u64 t; cvta.to.shared.u64 t, %1; cvt.u32.u64 %0, t; }"
        : "=r"(a) : "l"(p));
    return a;
}
__device__ __forceinline__ void cpa16(uint32_t s, const void* g) {
    asm volatile("cp.async.cg.shared.global [%0], [%1], 16;" :: "r"(s), "l"(g));
}
__device__ __forceinline__ void cpa_commit() {
    asm volatile("cp.async.commit_group;" ::: "memory");
}
__device__ __forceinline__ void cpa_wait1() {
    asm volatile("cp.async.wait_group 1;" ::: "memory");
}
__device__ __forceinline__ void cpa_wait0() {
    asm volatile("cp.async.wait_group 0;" ::: "memory");
}
__device__ __forceinline__ void ldsm4(uint32_t a, uint32_t* r) {
    asm volatile("ldmatrix.sync.aligned.m8n8.x4.shared.b16 {%0,%1,%2,%3}, [%4];"
                 : "=r"(r[0]), "=r"(r[1]), "=r"(r[2]), "=r"(r[3]) : "r"(a));
}
__device__ __forceinline__ void ldsm4t(uint32_t a, uint32_t* r) {
    asm volatile("ldmatrix.sync.aligned.m8n8.x4.trans.shared.b16 {%0,%1,%2,%3}, [%4];"
                 : "=r"(r[0]), "=r"(r[1]), "=r"(r[2]), "=r"(r[3]) : "r"(a));
}
__device__ __forceinline__ void mma16816(float* c, const uint32_t* a,
                                         uint32_t b0, uint32_t b1) {
    asm volatile("mma.sync.aligned.m16n8k16.row.col.f32.bf16.bf16.f32 "
                 "{%0,%1,%2,%3}, {%4,%5,%6,%7}, {%8,%9}, {%0,%1,%2,%3};"
                 : "+f"(c[0]), "+f"(c[1]), "+f"(c[2]), "+f"(c[3])
                 : "r"(a[0]), "r"(a[1]), "r"(a[2]), "r"(a[3]), "r"(b0), "r"(b1));
}
__device__ __forceinline__ float sigmoidf_(float x) { return 1.0f / (1.0f + expf(-x)); }
__device__ __forceinline__ void split1(float v, __nv_bfloat16& h, __nv_bfloat16& l) {
    h = __float2bfloat16_rn(v);
    l = __float2bfloat16_rn(v - __bfloat162float(h));
}
__device__ __forceinline__ uint32_t swz(uint32_t off) {
    return off ^ ((off >> 3) & 0x70);
}

// ---------------- grid barrier (all 128 blocks resident) ----------------
__device__ __forceinline__ void grid_barrier() {
    __syncthreads();
    if (threadIdx.x == 0) {
        __threadfence();
        unsigned gen = *((volatile unsigned*)&g_bar_gen);
        if (atomicAdd(&g_bar_arrive, 1u) == NBLK - 1) {
            g_bar_arrive = 0;
            __threadfence();
            atomicAdd(&g_bar_gen, 1u);
        } else {
            while (*((volatile unsigned*)&g_bar_gen) == gen) { __nanosleep(20); }
        }
        __threadfence();
    }
    __syncthreads();
}

// ---------------- persistent kernel ----------------
__global__ void __launch_bounds__(NTHR, 1)
lstm_hmma(const float* __restrict__ input,   // [512,64,1024]
          const float* __restrict__ h0,      // [2,64,1024]
          const float* __restrict__ c0,      // [2,64,1024]
          const float* __restrict__ W,       // [2,2048,4096]
          const float* __restrict__ bias,    // [2,4096]
          float* __restrict__ out)
{
    extern __shared__ __align__(1024) char dsm[];
    const uint32_t sbase = smem_u32(dsm);
    float* Rm = reinterpret_cast<float*>(dsm);            // gates [64][66]
    float* Sm = reinterpret_cast<float*>(dsm + 16896);    // kk scratch

    __shared__ float s_tr[32][33];
    __shared__ float s_hn[16][64];

    const int tid  = threadIdx.x;
    const int wid  = tid >> 5;
    const int lane = tid & 31;
    const int bid  = blockIdx.x;
    const int gid  = bid * NTHR + tid;
    const int lay  = bid >> 6;        // 0: layer0@s, 1: layer1@(s-1)
    const int mt   = bid & 63;        // M tile: rows [mt*64, +64)
    const int m0   = mt * 64;
    const int u0   = mt * 16;         // 16 cell-owned units of this layer

    // warp mapping: kg = kk index (4-way K16 split), pos -> (mq, nh) m32n32
    const int kg   = wid >> 2;        // 0..3
    const int wpos = wid & 3;
    const int mq   = wpos >> 1;       // m offset mq*32
    const int nh   = wpos & 1;        // n offset nh*32

    // ======== phase 0a: x transpose [t][b][u] -> [t][u][b] + bf16 split ====
    for (int tile = bid; tile < SEQ * 64; tile += NBLK) {
        const int t  = tile >> 6;
        const int ut = (tile >> 1) & 31;
        const int bt = tile & 1;
        const int ub = ut * 32, bb = bt * 32;
#pragma unroll
        for (int it = 0; it < 2; it++) {
            int r = (tid >> 5) + it * 16, c = lane;
            s_tr[r][c] = input[((size_t)t * 64 + bb + r) * HID + ub + c];
        }
        __syncthreads();
#pragma unroll
        for (int it = 0; it < 2; it++) {
            int i = (tid >> 5) + it * 16, j = lane;
            __nv_bfloat16 hv, lv;
            split1(s_tr[j][i], hv, lv);
            size_t dst = ((size_t)t * HID + ub + i) * 64 + bb + j;
            g_xhi[dst] = hv;
            g_xlo[dst] = lv;
        }
        __syncthreads();
    }
    // ======== phase 0b: W transpose + gate-permute + split ========
    for (int tile = bid; tile < 2 * 64 * 128; tile += NBLK) {
        const int l  = tile >> 13;
        const int kt = (tile & 8191) >> 7;
        const int nt = tile & 127;
        const int k0 = kt * 32, n0 = nt * 32;
#pragma unroll
        for (int r = 0; r < 2; r++) {
            int kk = (tid >> 5) + r * 16;
            s_tr[kk][lane] = W[((size_t)l * KTOT + k0 + kk) * NOUT + n0 + lane];
        }
        __syncthreads();
#pragma unroll
        for (int r = 0; r < 2; r++) {
            int j = (tid >> 5) + r * 16;
            int n = n0 + j;
            int p = ((n & 1023) << 2) | (n >> 10);
            __nv_bfloat16 hv, lv;
            split1(s_tr[lane][j], hv, lv);
            size_t dst = ((size_t)l * NOUT + p) * KTOT + k0 + lane;
            g_wthi[dst] = hv;
            g_wtlo[dst] = lv;
        }
        __syncthreads();
    }
    // ======== phase 0c: seed h (parity: l0->par0, l1->par1) and c =========
    for (int tile = bid; tile < 256; tile += NBLK) {
        const int kind = tile >> 7;
        const int rest = tile & 127;
        const int l  = rest >> 6;
        const int ut = (rest >> 1) & 31;
        const int bt = rest & 1;
        const int ub = ut * 32, bb = bt * 32;
        const float* src = (kind == 0) ? h0 : c0;
#pragma unroll
        for (int it = 0; it < 2; it++) {
            int r = (tid >> 5) + it * 16, c = lane;
            s_tr[r][c] = src[((size_t)l * 64 + bb + r) * HID + ub + c];
        }
        __syncthreads();
#pragma unroll
        for (int it = 0; it < 2; it++) {
            int i = (tid >> 5) + it * 16, j = lane;
            float v = s_tr[j][i];
            if (kind == 0) {
                __nv_bfloat16 hv, lv;
                split1(v, hv, lv);
                const int buf = (l == 0) ? 0 : 3;   // (par0,l0)=0, (par1,l1)=3
                size_t dst = (size_t)buf * BH + (size_t)(ub + i) * 64 + bb + j;
                g_hhi[dst] = hv;
                g_hlo[dst] = lv;
            } else {
                g_c[(size_t)l * BH + (size_t)(ub + i) * 64 + bb + j] = v;
            }
        }
        __syncthreads();
    }
    grid_barrier();

    // ---- lane-constant ldmatrix row bases + swizzle XORs ----
    const int q  = lane >> 3, r8 = lane & 7;
    const int rowA = mq * 32 + r8 + (q & 1) * 8;      // +16 for mi=1
    const uint32_t baseA = (uint32_t)rowA * 128;
    const uint32_t xorA  = (uint32_t)(rowA & 7) * 16;
    const int rowB = kg * 16 + (q & 1) * 8 + r8;      // this warp's k16 rows
    const uint32_t baseB = (uint32_t)rowB * 128;
    const uint32_t xorB  = (uint32_t)(rowB & 7) * 16;
    const uint32_t colq  = (uint32_t)(q >> 1) * 16;
    const uint32_t aoffc = (colq + (uint32_t)kg * 32) ^ xorA;  // A col fixed/warp

    // W pointers fixed for this CTA
    const __nv_bfloat16* Wh = g_wthi + ((size_t)lay * NOUT + m0) * KTOT;
    const __nv_bfloat16* Wo = g_wtlo + ((size_t)lay * NOUT + m0) * KTOT;

    // ======== main recurrence: 513 super-steps, ONE barrier each ========
    for (int s = 0; s <= SEQ; s++) {
        const int par = s & 1;
        const bool active = (lay == 0) ? (s < SEQ) : (s >= 1);

        if (active) {
            // ---- B sources: first 1024 k and second 1024 k ----
            const __nv_bfloat16 *B0h, *B0l, *B1h, *B1l;
            if (lay == 0) {
                B0h = g_xhi + (size_t)s * BH;  B0l = g_xlo + (size_t)s * BH;
                B1h = g_hhi + (size_t)(par * 2 + 0) * BH;
                B1l = g_hlo + (size_t)(par * 2 + 0) * BH;
            } else {
                B0h = g_hhi + (size_t)(par * 2 + 0) * BH;
                B0l = g_hlo + (size_t)(par * 2 + 0) * BH;
                B1h = g_hhi + (size_t)(par * 2 + 1) * BH;
                B1l = g_hlo + (size_t)(par * 2 + 1) * BH;
            }

            auto issueW = [&](int kc, uint32_t st) {
                int row = tid >> 3, c8 = tid & 7;
                uint32_t off = swz((uint32_t)row * 128 + c8 * 16);
                size_t go = (size_t)row * KTOT + kc + c8 * 8;
                cpa16(st + off, Wh + go);
                cpa16(st + 8192 + off, Wo + go);
            };
            auto issueB = [&](int kc, uint32_t st) {
                int row = tid >> 3, c8 = tid & 7;
                uint32_t off = swz((uint32_t)row * 128 + c8 * 16);
                const __nv_bfloat16 *bh_, *bl_;
                int kr;
                if (kc < 1024) { bh_ = B0h; bl_ = B0l; kr = kc; }
                else           { bh_ = B1h; bl_ = B1l; kr = kc - 1024; }
                size_t go = (size_t)(kr + row) * 64 + c8 * 8;
                cpa16(st + 16384 + off, bh_ + go);
                cpa16(st + 24576 + off, bl_ + go);
            };

            float acc[2][4][4];
#pragma unroll
            for (int i = 0; i < 2; i++)
#pragma unroll
                for (int j = 0; j < 4; j++)
#pragma unroll
                    for (int r = 0; r < 4; r++) acc[i][j][r] = 0.0f;

            // prologue: chunks 0,1
            issueW(0, sbase);        issueB(0, sbase);        cpa_commit();
            issueW(CHK, sbase + STGB); issueB(CHK, sbase + STGB); cpa_commit();

            for (int ch = 0; ch < NCHK; ch++) {
                if (ch < NCHK - 1) cpa_wait1(); else cpa_wait0();
                __syncthreads();     // stage ch ready; stage (ch+2)%3 reusable
                if (ch + 2 < NCHK) {
                    const uint32_t st = sbase + ((ch + 2) % NSTG) * STGB;
                    issueW((ch + 2) * CHK, st);
                    issueB((ch + 2) * CHK, st);
                    cpa_commit();
                }

                // ---- compute chunk ch (this warp's kk = kg) ----
                const uint32_t st = sbase + (ch % NSTG) * STGB;
                uint32_t ahi0[4], ahi1[4], alo0[4], alo1[4];
                ldsm4(st + baseA + aoffc, ahi0);
                ldsm4(st + baseA + 2048 + aoffc, ahi1);
                ldsm4(st + 8192 + baseA + aoffc, alo0);
                ldsm4(st + 8192 + baseA + 2048 + aoffc, alo1);
#pragma unroll
                for (int pl = 0; pl < 2; pl++) {
                    const int p = nh * 2 + pl;
                    const uint32_t boff = baseB + ((colq + (uint32_t)p * 32) ^ xorB);
                    uint32_t bh[4], bl[4];
                    ldsm4t(st + 16384 + boff, bh);
                    ldsm4t(st + 24576 + boff, bl);
                    mma16816(acc[0][2 * pl],     ahi0, bh[0], bh[1]);
                    mma16816(acc[0][2 * pl],     ahi0, bl[0], bl[1]);
                    mma16816(acc[0][2 * pl],     alo0, bh[0], bh[1]);
                    mma16816(acc[0][2 * pl + 1], ahi0, bh[2], bh[3]);
                    mma16816(acc[0][2 * pl + 1], ahi0, bl[2], bl[3]);
                    mma16816(acc[0][2 * pl + 1], alo0, bh[2], bh[3]);
                    mma16816(acc[1][2 * pl],     ahi1, bh[0], bh[1]);
                    mma16816(acc[1][2 * pl],     ahi1, bl[0], bl[1]);
                    mma16816(acc[1][2 * pl],     alo1, bh[0], bh[1]);
                    mma16816(acc[1][2 * pl + 1], ahi1, bh[2], bh[3]);
                    mma16816(acc[1][2 * pl + 1], ahi1, bl[2], bl[3]);
                    mma16816(acc[1][2 * pl + 1], alo1, bh[2], bh[3]);
                }
            }
            __syncthreads();   // all computes done; stage smem reusable

            // ---- kk reduction: kg1..3 store to scratch ----
            if (kg != 0) {
                float* sp = Sm + ((size_t)((kg - 1) * 4 + wpos)) * 1024 + lane;
#pragma unroll
                for (int i = 0; i < 2; i++)
#pragma unroll
                    for (int j = 0; j < 4; j++)
#pragma unroll
                        for (int r = 0; r < 4; r++)
                            sp[((i * 4 + j) * 4 + r) * 32] = acc[i][j][r];
            }
            __syncthreads();

            // ---- kg0 sums all kk, writes gates to Rm[64][66] ----
            if (kg == 0) {
                const int g4 = lane >> 2;
                const int tt = lane & 3;
#pragma unroll
                for (int i = 0; i < 2; i++) {
#pragma unroll
                    for (int j = 0; j < 4; j++) {
                        float o[4];
#pragma unroll
                        for (int r = 0; r < 4; r++) {
                            float v = acc[i][j][r];
#pragma unroll
                            for (int sset = 0; sset < 3; sset++)
                                v += Sm[((size_t)(sset * 4 + wpos)) * 1024
                                        + ((i * 4 + j) * 4 + r) * 32 + lane];
                            o[r] = v;
                        }
                        const int row = mq * 32 + i * 16 + g4;
                        const int col = nh * 32 + j * 8 + 2 * tt;
                        Rm[row * 66 + col]       = o[0];
                        Rm[row * 66 + col + 1]   = o[1];
                        Rm[(row + 8) * 66 + col]     = o[2];
                        Rm[(row + 8) * 66 + col + 1] = o[3];
                    }
                }
            }
            __syncthreads();

            // ---- CTA-local cell: 16 units x 64 batches ----
#pragma unroll
            for (int half = 0; half < 2; half++) {
                const int item = tid + half * NTHR;   // 0..1023
                const int ul = item >> 6;             // 0..15
                const int b  = item & 63;
                const int u  = u0 + ul;
                float gv[4];
#pragma unroll
                for (int gate = 0; gate < 4; gate++)
                    gv[gate] = bias[(size_t)lay * NOUT + gate * 1024 + u]
                             + Rm[(ul * 4 + gate) * 66 + b];
                const size_t cidx = (size_t)lay * BH + (size_t)u * 64 + b;
                const float gi = sigmoidf_(gv[0]);
                const float gj = tanhf(gv[1]);
                const float gf = sigmoidf_(gv[2]);
                const float go = sigmoidf_(gv[3]);
                const float cn = g_c[cidx] * gf + gi * gj;
                g_c[cidx] = cn;
                const float hn = tanhf(cn) * go;
                g_hf[cidx] = hn;
                __nv_bfloat16 hv, lv;
                split1(hn, hv, lv);
                const size_t hidx = (size_t)(((par ^ 1) * 2) + lay) * BH
                                  + (size_t)u * 64 + b;
                g_hhi[hidx] = hv;
                g_hlo[hidx] = lv;
                if (lay == 1) s_hn[ul][b] = hn;
            }

            // ---- layer1: write final_output[s-1] ----
            if (lay == 1) {
                __syncthreads();
                if (tid < 256) {
                    const int b = tid >> 2, qq = tid & 3;
                    float4 v = make_float4(s_hn[qq * 4 + 0][b], s_hn[qq * 4 + 1][b],
                                           s_hn[qq * 4 + 2][b], s_hn[qq * 4 + 3][b]);
                    reinterpret_cast<float4*>(
                        out + (size_t)(s - 1) * BH + (size_t)b * HID + u0)[qq] = v;
                }
            }
        }
        grid_barrier();
    }

    // ======== tail: last_hidden + last_cell, de-transpose ========
    for (int i = gid; i < 2 * BH; i += GTH) {
        int l = i >> 16, rr = i & 65535, b = rr >> 10, u = rr & 1023;
        out[(size_t)SEQ * BH + i] = g_hf[(size_t)l * BH + (size_t)u * 64 + b];
        out[(size_t)SEQ * BH + 2 * BH + i] = g_c[(size_t)l * BH + (size_t)u * 64 + b];
    }
}

// ---------------- launch: ONE graph node ----------------
extern "C" void kernel_launch(void* const* d_in, const int* in_sizes, int n_in,
                              void* d_out, int out_size) {
    const float* input = (const float*)d_in[0];
    const float* h0    = (const float*)d_in[1];
    const float* c0    = (const float*)d_in[2];
    const float* W     = (const float*)d_in[3];
    const float* bias  = (const float*)d_in[4];
    float* out = (float*)d_out;

    cudaFuncSetAttribute(lstm_hmma, cudaFuncAttributeMaxDynamicSharedMemorySize, DSMEM);
    lstm_hmma<<<NBLK, NTHR, DSMEM>>>(input, h0, c0, W, bias, out);
}

// round 10
// speedup vs baseline: 1.0233x; 1.0233x over previous
#include <cuda_runtime.h>
#include <cuda_bf16.h>
#include <cstdint>

// BasicLSTM via mma.sync (HMMA bf16, 3-term fp32-split emulation).
// SEQ=512, BATCH=64, HID=1024, LAYERS=2.
// R10 = R8 (wavefront layers, M=128 tiles, split-K=2) + 3-stage cp.async
// pipeline with ONE __syncthreads per chunk + hoisted issue addressing.

#define SEQ    512
#define BATCH  64
#define HID    1024
#define KTOT   2048
#define NOUT   4096
#define BH     (BATCH * HID)        // 65536
#define NBLK   128
#define NTHR   512
#define GTH    (NBLK * NTHR)
#define KSL    1024                 // K per slice (2 slices per layer)
#define CHK    64                   // K per chunk
#define NCHK   (KSL / CHK)          // 16
#define STGB   49152                // Ahi16K | Alo16K | Bhi8K | Blo8K
#define NSTG   3
#define DSMEM  (NSTG * STGB)        // 147456

// ---------------- device globals (no allocs) ----------------
__device__ __align__(128) __nv_bfloat16 g_xhi[(size_t)SEQ * HID * 64];
__device__ __align__(128) __nv_bfloat16 g_xlo[(size_t)SEQ * HID * 64];
__device__ __align__(128) __nv_bfloat16 g_wthi[(size_t)2 * NOUT * KTOT]; // [l][p][k]
__device__ __align__(128) __nv_bfloat16 g_wtlo[(size_t)2 * NOUT * KTOT];
__device__ __align__(128) __nv_bfloat16 g_hhi[2 * BH];    // [l][u][b] single-buffered
__device__ __align__(128) __nv_bfloat16 g_hlo[2 * BH];
__device__ __align__(128) float g_partial[(size_t)4 * NOUT * 64]; // [lay*2+ks][p][b]
__device__ __align__(128) float g_c[2 * BH];              // [l][u][b]
__device__ __align__(128) float g_hf[2 * BH];             // [l][u][b]
__device__ unsigned g_bar_arrive;
__device__ unsigned g_bar_gen;

// ---------------- PTX helpers ----------------
__device__ __forceinline__ uint32_t smem_u32(const void* p) {
    uint32_t a;
    asm("{ .reg .u64 t; cvta.to.shared.u64 t, %1; cvt.u32.u64 %0, t; }"
        : "=r"(a) : "l"(p));
    return a;
}
__device__ __forceinline__ void cpa16(uint32_t s, const void* g) {
    asm volatile("cp.async.cg.shared.global [%0], [%1], 16;" :: "r"(s), "l"(g));
}
__device__ __forceinline__ void cpa_commit() {
    asm volatile("cp.async.commit_group;" ::: "memory");
}
__device__ __forceinline__ void cpa_wait1() {
    asm volatile("cp.async.wait_group 1;" ::: "memory");
}
__device__ __forceinline__ void cpa_wait0() {
    asm volatile("cp.async.wait_group 0;" ::: "memory");
}
__device__ __forceinline__ void ldsm4(uint32_t a, uint32_t* r) {
    asm volatile("ldmatrix.sync.aligned.m8n8.x4.shared.b16 {%0,%1,%2,%3}, [%4];"
                 : "=r"(r[0]), "=r"(r[1]), "=r"(r[2]), "=r"(r[3]) : "r"(a));
}
__device__ __forceinline__ void ldsm4t(uint32_t a, uint32_t* r) {
    asm volatile("ldmatrix.sync.aligned.m8n8.x4.trans.shared.b16 {%0,%1,%2,%3}, [%4];"
                 : "=r"(r[0]), "=r"(r[1]), "=r"(r[2]), "=r"(r[3]) : "r"(a));
}
__device__ __forceinline__ void mma16816(float* c, const uint32_t* a,
                                         uint32_t b0, uint32_t b1) {
    asm volatile("mma.sync.aligned.m16n8k16.row.col.f32.bf16.bf16.f32 "
                 "{%0,%1,%2,%3}, {%4,%5,%6,%7}, {%8,%9}, {%0,%1,%2,%3};"
                 : "+f"(c[0]), "+f"(c[1]), "+f"(c[2]), "+f"(c[3])
                 : "r"(a[0]), "r"(a[1]), "r"(a[2]), "r"(a[3]), "r"(b0), "r"(b1));
}
__device__ __forceinline__ float sigmoidf_(float x) { return 1.0f / (1.0f + expf(-x)); }
__device__ __forceinline__ void split1(float v, __nv_bfloat16& h, __nv_bfloat16& l) {
    h = __float2bfloat16_rn(v);
    l = __float2bfloat16_rn(v - __bfloat162float(h));
}
__device__ __forceinline__ uint32_t swz(uint32_t off) {
    return off ^ ((off >> 3) & 0x70);
}

// ---------------- grid barrier (all 128 blocks resident) ----------------
__device__ __forceinline__ void grid_barrier() {
    __syncthreads();
    if (threadIdx.x == 0) {
        __threadfence();
        unsigned gen = *((volatile unsigned*)&g_bar_gen);
        if (atomicAdd(&g_bar_arrive, 1u) == NBLK - 1) {
            g_bar_arrive = 0;
            __threadfence();
            atomicAdd(&g_bar_gen, 1u);
        } else {
            while (*((volatile unsigned*)&g_bar_gen) == gen) { __nanosleep(20); }
        }
        __threadfence();
    }
    __syncthreads();
}

// ---------------- persistent kernel ----------------
__global__ void __launch_bounds__(NTHR, 1)
lstm_hmma(const float* __restrict__ input,   // [512,64,1024]
          const float* __restrict__ h0,      // [2,64,1024]
          const float* __restrict__ c0,      // [2,64,1024]
          const float* __restrict__ W,       // [2,2048,4096]
          const float* __restrict__ bias,    // [2,4096]
          float* __restrict__ out)
{
    extern __shared__ __align__(1024) char dsm[];
    const uint32_t sbase = smem_u32(dsm);

    __shared__ float s_tr[32][33];
    __shared__ float s_hn[8][64];

    const int tid  = threadIdx.x;
    const int wid  = tid >> 5;
    const int lane = tid & 31;
    const int bid  = blockIdx.x;
    const int gid  = bid * NTHR + tid;
    const int lay  = bid >> 6;        // 0: layer0@s, 1: layer1@(s-1)
    const int cg   = bid & 31;        // M tile: rows [cg*128, +128)
    const int ks   = (bid >> 5) & 1;  // K slice: [ks*1024, +1024)
    const int pgrp = bid >> 5;        // partial group: lay*2+ks
    const int m0   = cg * 128;
    const int u0   = bid * 8;         // cell-owned units (both layers)

    // warp mapping: kg = k-group (kk pair), wpos -> (mq, nh) m32n32 tile
    const int kg   = wid >> 3;        // 0: kk{0,1}, 1: kk{2,3}
    const int wpos = wid & 7;
    const int mq   = wpos >> 1;       // m offset mq*32
    const int nh   = wpos & 1;        // n offset nh*32

    // ======== phase 0a: x transpose [t][b][u] -> [t][u][b] + bf16 split ====
    for (int tile = bid; tile < SEQ * 64; tile += NBLK) {
        const int t  = tile >> 6;
        const int ut = (tile >> 1) & 31;
        const int bt = tile & 1;
        const int ub = ut * 32, bb = bt * 32;
#pragma unroll
        for (int it = 0; it < 2; it++) {
            int r = (tid >> 5) + it * 16, c = lane;
            s_tr[r][c] = input[((size_t)t * 64 + bb + r) * HID + ub + c];
        }
        __syncthreads();
#pragma unroll
        for (int it = 0; it < 2; it++) {
            int i = (tid >> 5) + it * 16, j = lane;
            __nv_bfloat16 hv, lv;
            split1(s_tr[j][i], hv, lv);
            size_t dst = ((size_t)t * HID + ub + i) * 64 + bb + j;
            g_xhi[dst] = hv;
            g_xlo[dst] = lv;
        }
        __syncthreads();
    }
    // ======== phase 0b: W transpose + gate-permute + split ========
    for (int tile = bid; tile < 2 * 64 * 128; tile += NBLK) {
        const int l  = tile >> 13;
        const int kt = (tile & 8191) >> 7;
        const int nt = tile & 127;
        const int k0 = kt * 32, n0 = nt * 32;
#pragma unroll
        for (int r = 0; r < 2; r++) {
            int kk = (tid >> 5) + r * 16;
            s_tr[kk][lane] = W[((size_t)l * KTOT + k0 + kk) * NOUT + n0 + lane];
        }
        __syncthreads();
#pragma unroll
        for (int r = 0; r < 2; r++) {
            int j = (tid >> 5) + r * 16;
            int n = n0 + j;
            int p = ((n & 1023) << 2) | (n >> 10);
            __nv_bfloat16 hv, lv;
            split1(s_tr[lane][j], hv, lv);
            size_t dst = ((size_t)l * NOUT + p) * KTOT + k0 + lane;
            g_wthi[dst] = hv;
            g_wtlo[dst] = lv;
        }
        __syncthreads();
    }
    // ======== phase 0c: seed h (transposed, split) and c (transposed) =====
    for (int tile = bid; tile < 256; tile += NBLK) {
        const int kind = tile >> 7;
        const int rest = tile & 127;
        const int l  = rest >> 6;
        const int ut = (rest >> 1) & 31;
        const int bt = rest & 1;
        const int ub = ut * 32, bb = bt * 32;
        const float* src = (kind == 0) ? h0 : c0;
#pragma unroll
        for (int it = 0; it < 2; it++) {
            int r = (tid >> 5) + it * 16, c = lane;
            s_tr[r][c] = src[((size_t)l * 64 + bb + r) * HID + ub + c];
        }
        __syncthreads();
#pragma unroll
        for (int it = 0; it < 2; it++) {
            int i = (tid >> 5) + it * 16, j = lane;
            float v = s_tr[j][i];
            if (kind == 0) {
                __nv_bfloat16 hv, lv;
                split1(v, hv, lv);
                size_t dst = (size_t)l * BH + (size_t)(ub + i) * 64 + bb + j;
                g_hhi[dst] = hv;
                g_hlo[dst] = lv;
            } else {
                g_c[(size_t)l * BH + (size_t)(ub + i) * 64 + bb + j] = v;
            }
        }
        __syncthreads();
    }
    grid_barrier();

    // ---- lane-constant ldmatrix row bases + swizzle XORs ----
    const int q  = lane >> 3, r8 = lane & 7;
    const int rowA = mq * 32 + r8 + (q & 1) * 8;
    const uint32_t baseA = (uint32_t)rowA * 128;
    const uint32_t xorA  = (uint32_t)(rowA & 7) * 16;
    const int rowB = (q & 1) * 8 + r8;
    const uint32_t baseB = (uint32_t)rowB * 128;
    const uint32_t xorB  = (uint32_t)(rowB & 7) * 16;
    const uint32_t colq  = (uint32_t)(q >> 1) * 16;

    // ---- hoisted cp.async addressing (lane-constant) ----
    const int irow = tid >> 3;                 // 0..63
    const int ic8  = (tid & 7) * 8;            // element offset within row
    const uint32_t offL0 = swz((uint32_t)irow * 128 + (tid & 7) * 16);
    const uint32_t offL1 = swz((uint32_t)(irow + 64) * 128 + (tid & 7) * 16);

    // W pointers fixed for this CTA (per-thread bases)
    const __nv_bfloat16* WhP0 = g_wthi + ((size_t)lay * NOUT + m0 + irow) * KTOT
                              + ks * KSL + ic8;
    const __nv_bfloat16* WhP1 = WhP0 + (size_t)64 * KTOT;
    const __nv_bfloat16* WoP0 = g_wtlo + ((size_t)lay * NOUT + m0 + irow) * KTOT
                              + ks * KSL + ic8;
    const __nv_bfloat16* WoP1 = WoP0 + (size_t)64 * KTOT;

    // ======== main recurrence: 513 super-steps ========
    for (int s = 0; s <= SEQ; s++) {
        const bool do_l0 = (s < SEQ);
        const bool do_l1 = (s >= 1);
        const bool active = (lay == 0) ? do_l0 : do_l1;

        if (active) {
            // ---- B operand selection (per-thread base pointers) ----
            const __nv_bfloat16 *Bh, *Bl;
            if (lay == 0) {
                if (ks == 0) { Bh = g_xhi + (size_t)s * BH; Bl = g_xlo + (size_t)s * BH; }
                else         { Bh = g_hhi;                  Bl = g_hlo; }
            } else {
                if (ks == 0) { Bh = g_hhi;      Bl = g_hlo; }
                else         { Bh = g_hhi + BH; Bl = g_hlo + BH; }
            }
            const __nv_bfloat16* BhP = Bh + (size_t)tid * 8;
            const __nv_bfloat16* BlP = Bl + (size_t)tid * 8;

            float acc[2][4][4];
#pragma unroll
            for (int i = 0; i < 2; i++)
#pragma unroll
                for (int j = 0; j < 4; j++)
#pragma unroll
                    for (int r = 0; r < 4; r++) acc[i][j][r] = 0.0f;

            // prologue: chunks 0,1
#pragma unroll
            for (int pc = 0; pc < 2; pc++) {
                const uint32_t st = sbase + pc * STGB;
                const int kc = pc * CHK;
                cpa16(st + offL0,         WhP0 + kc);
                cpa16(st + 16384 + offL0, WoP0 + kc);
                cpa16(st + offL1,         WhP1 + kc);
                cpa16(st + 16384 + offL1, WoP1 + kc);
                cpa16(st + 32768 + offL0, BhP + kc * 64);
                cpa16(st + 40960 + offL0, BlP + kc * 64);
                cpa_commit();
            }

            for (int ch = 0; ch < NCHK; ch++) {
                if (ch < NCHK - 1) cpa_wait1(); else cpa_wait0();
                __syncthreads();     // stage ch ready; stage (ch+2)%3 reusable
                if (ch + 2 < NCHK) {
                    const uint32_t st = sbase + ((ch + 2) % NSTG) * STGB;
                    const int kc = (ch + 2) * CHK;
                    cpa16(st + offL0,         WhP0 + kc);
                    cpa16(st + 16384 + offL0, WoP0 + kc);
                    cpa16(st + offL1,         WhP1 + kc);
                    cpa16(st + 16384 + offL1, WoP1 + kc);
                    cpa16(st + 32768 + offL0, BhP + kc * 64);
                    cpa16(st + 40960 + offL0, BlP + kc * 64);
                    cpa_commit();
                }

                // ---- compute chunk ch (this warp's 2 kk of 4) ----
                const uint32_t st = sbase + (ch % NSTG) * STGB;
#pragma unroll
                for (int kk2 = 0; kk2 < 2; kk2++) {
                    const int kk = kg * 2 + kk2;
                    const uint32_t aoff = (colq + kk * 32) ^ xorA;
                    uint32_t ahi0[4], ahi1[4], alo0[4], alo1[4];
                    ldsm4(st + baseA + aoff, ahi0);
                    ldsm4(st + baseA + 2048 + aoff, ahi1);
                    ldsm4(st + 16384 + baseA + aoff, alo0);
                    ldsm4(st + 16384 + baseA + 2048 + aoff, alo1);
#pragma unroll
                    for (int pl = 0; pl < 2; pl++) {
                        const int p = nh * 2 + pl;
                        const uint32_t boff = baseB + (uint32_t)kk * 2048
                                            + ((colq + p * 32) ^ xorB);
                        uint32_t bh[4], bl[4];
                        ldsm4t(st + 32768 + boff, bh);
                        ldsm4t(st + 40960 + boff, bl);
                        mma16816(acc[0][2 * pl],     ahi0, bh[0], bh[1]);
                        mma16816(acc[0][2 * pl],     ahi0, bl[0], bl[1]);
                        mma16816(acc[0][2 * pl],     alo0, bh[0], bh[1]);
                        mma16816(acc[0][2 * pl + 1], ahi0, bh[2], bh[3]);
                        mma16816(acc[0][2 * pl + 1], ahi0, bl[2], bl[3]);
                        mma16816(acc[0][2 * pl + 1], alo0, bh[2], bh[3]);
                        mma16816(acc[1][2 * pl],     ahi1, bh[0], bh[1]);
                        mma16816(acc[1][2 * pl],     ahi1, bl[0], bl[1]);
                        mma16816(acc[1][2 * pl],     alo1, bh[0], bh[1]);
                        mma16816(acc[1][2 * pl + 1], ahi1, bh[2], bh[3]);
                        mma16816(acc[1][2 * pl + 1], ahi1, bl[2], bl[3]);
                        mma16816(acc[1][2 * pl + 1], alo1, bh[2], bh[3]);
                    }
                }
            }
            __syncthreads();   // all computes done; stage smem reusable

            // ---- k-group reduction via (reused) stage-0 smem ----
            if (kg == 1) {
                const uint32_t rb = sbase + (uint32_t)wpos * 4096 + (uint32_t)lane * 4;
#pragma unroll
                for (int i = 0; i < 2; i++)
#pragma unroll
                    for (int j = 0; j < 4; j++)
#pragma unroll
                        for (int r = 0; r < 4; r++) {
                            asm volatile("st.shared.b32 [%0], %1;"
                                :: "r"(rb + ((i * 4 + j) * 4 + r) * 128),
                                   "f"(acc[i][j][r]) : "memory");
                        }
            }
            __syncthreads();

            if (kg == 0) {
                const uint32_t rb = sbase + (uint32_t)wpos * 4096 + (uint32_t)lane * 4;
                const int g4 = lane >> 2;
                const int tt = lane & 3;
#pragma unroll
                for (int i = 0; i < 2; i++) {
#pragma unroll
                    for (int j = 0; j < 4; j++) {
                        float o[4];
#pragma unroll
                        for (int r = 0; r < 4; r++) {
                            float v;
                            asm volatile("ld.shared.b32 %0, [%1];"
                                : "=f"(v)
                                : "r"(rb + ((i * 4 + j) * 4 + r) * 128));
                            o[r] = acc[i][j][r] + v;
                        }
                        const int prow = m0 + mq * 32 + i * 16 + g4;
                        const int col  = nh * 32 + j * 8 + 2 * tt;
                        float* pp = g_partial + ((size_t)pgrp * NOUT + prow) * 64 + col;
                        *reinterpret_cast<float2*>(pp) = make_float2(o[0], o[1]);
                        *reinterpret_cast<float2*>(pp + 8 * 64) = make_float2(o[2], o[3]);
                    }
                }
            }
        }
        grid_barrier();

        // ---- cell phase: both layers, 8 units x 64 batches per CTA ----
        {
            const int b  = tid & 63;
            const int ul = tid >> 6;            // 0..7
            const int u  = u0 + ul;
#pragma unroll
            for (int cl = 0; cl < 2; cl++) {
                if (cl == 0 ? !do_l0 : !do_l1) continue;
                float gv[4];
#pragma unroll
                for (int gate = 0; gate < 4; gate++) {
                    const int p = 4 * u + gate;
                    float sum = bias[(size_t)cl * NOUT + gate * 1024 + u];
                    sum += g_partial[((size_t)(cl * 2 + 0) * NOUT + p) * 64 + b];
                    sum += g_partial[((size_t)(cl * 2 + 1) * NOUT + p) * 64 + b];
                    gv[gate] = sum;
                }
                const size_t cidx = (size_t)cl * BH + (size_t)u * 64 + b;
                const float gi = sigmoidf_(gv[0]);
                const float gj = tanhf(gv[1]);
                const float gf = sigmoidf_(gv[2]);
                const float go = sigmoidf_(gv[3]);
                const float cn = g_c[cidx] * gf + gi * gj;
                g_c[cidx] = cn;
                const float hn = tanhf(cn) * go;
                g_hf[cidx] = hn;
                __nv_bfloat16 hv, lv;
                split1(hn, hv, lv);
                g_hhi[cidx] = hv;
                g_hlo[cidx] = lv;
                if (cl == 1) s_hn[ul][b] = hn;
            }
            __syncthreads();
            if (do_l1 && tid < 64) {
                const int b2 = tid;
                float* op = out + (size_t)(s - 1) * BH + (size_t)b2 * HID + u0;
                reinterpret_cast<float4*>(op)[0] =
                    make_float4(s_hn[0][b2], s_hn[1][b2], s_hn[2][b2], s_hn[3][b2]);
                reinterpret_cast<float4*>(op)[1] =
                    make_float4(s_hn[4][b2], s_hn[5][b2], s_hn[6][b2], s_hn[7][b2]);
            }
        }
        grid_barrier();
    }

    // ======== tail: last_hidden + last_cell, de-transpose ========
    for (int i = gid; i < 2 * BH; i += GTH) {
        int l = i >> 16, rr = i & 65535, b = rr >> 10, u = rr & 1023;
        out[(size_t)SEQ * BH + i] = g_hf[(size_t)l * BH + (size_t)u * 64 + b];
        out[(size_t)SEQ * BH + 2 * BH + i] = g_c[(size_t)l * BH + (size_t)u * 64 + b];
    }
}

// ---------------- launch: ONE graph node ----------------
extern "C" void kernel_launch(void* const* d_in, const int* in_sizes, int n_in,
                              void* d_out, int out_size) {
    const float* input = (const float*)d_in[0];
    const float* h0    = (const float*)d_in[1];
    const float* c0    = (const float*)d_in[2];
    const float* W     = (const float*)d_in[3];
    const float* bias  = (const float*)d_in[4];
    float* out = (float*)d_out;

    cudaFuncSetAttribute(lstm_hmma, cudaFuncAttributeMaxDynamicSharedMemorySize, DSMEM);
    lstm_hmma<<<NBLK, NTHR, DSMEM>>>(input, h0, c0, W, bias, out);
}

// round 13
// speedup vs baseline: 1.0913x; 1.0665x over previous
#include <cuda_runtime.h>
#include <cuda_bf16.h>
#include <cstdint>

// BasicLSTM via mma.sync (HMMA bf16, 3-term fp32-split emulation).
// SEQ=512, BATCH=64, HID=1024, LAYERS=2.
// R13 = R12 with the deadlock fix: cp.async.mbarrier.arrive needs .noinc
// (default variant increments pending count first -> NET ZERO -> barrier
// never flips). Per-stage mbarrier producer/consumer pipeline so warps
// de-phase and ldsm (LDS) overlaps HMMA (tensor).

#define SEQ    512
#define BATCH  64
#define HID    1024
#define KTOT   2048
#define NOUT   4096
#define BH     (BATCH * HID)        // 65536
#define NBLK   128
#define NTHR   512
#define GTH    (NBLK * NTHR)
#define KSL    1024                 // K per slice (2 slices per layer)
#define CHK    64                   // K per chunk
#define NCHK   (KSL / CHK)          // 16
#define STGB   49152                // Ahi16K | Alo16K | Bhi8K | Blo8K
#define NSTG   3
#define DSMEM  (NSTG * STGB)        // 147456

// ---------------- device globals (no allocs) ----------------
__device__ __align__(128) __nv_bfloat16 g_xhi[(size_t)SEQ * HID * 64];
__device__ __align__(128) __nv_bfloat16 g_xlo[(size_t)SEQ * HID * 64];
__device__ __align__(128) __nv_bfloat16 g_wthi[(size_t)2 * NOUT * KTOT]; // [l][p][k]
__device__ __align__(128) __nv_bfloat16 g_wtlo[(size_t)2 * NOUT * KTOT];
__device__ __align__(128) __nv_bfloat16 g_hhi[2 * BH];    // [l][u][b] single-buffered
__device__ __align__(128) __nv_bfloat16 g_hlo[2 * BH];
__device__ __align__(128) float g_partial[(size_t)4 * NOUT * 64]; // [lay*2+ks][p][b]
__device__ __align__(128) float g_c[2 * BH];              // [l][u][b]
__device__ __align__(128) float g_hf[2 * BH];             // [l][u][b]
__device__ unsigned g_bar_arrive;
__device__ unsigned g_bar_gen;

// ---------------- PTX helpers ----------------
__device__ __forceinline__ uint32_t smem_u32(const void* p) {
    uint32_t a;
    asm("{ .reg .u64 t; cvta.to.shared.u64 t, %1; cvt.u32.u64 %0, t; }"
        : "=r"(a) : "l"(p));
    return a;
}
__device__ __forceinline__ void cpa16(uint32_t s, const void* g) {
    asm volatile("cp.async.cg.shared.global [%0], [%1], 16;" :: "r"(s), "l"(g));
}
// .noinc is load-bearing: default variant nets ZERO on the pending count.
__device__ __forceinline__ void cpa_mbar_arrive(uint32_t mbar) {
    asm volatile("cp.async.mbarrier.arrive.noinc.shared::cta.b64 [%0];"
                 :: "r"(mbar) : "memory");
}
__device__ __forceinline__ void mbar_init(uint32_t a, uint32_t cnt) {
    asm volatile("mbarrier.init.shared.b64 [%0], %1;" :: "r"(a), "r"(cnt) : "memory");
}
__device__ __forceinline__ void mbar_arrive(uint32_t a) {
    asm volatile("mbarrier.arrive.shared::cta.b64 _, [%0];" :: "r"(a) : "memory");
}
// Sleep-based wait (HW TRYWAIT): fast-path probe, then retry loop WITH the
// suspend hint so waiting warps become ineligible (no hi-wid starvation).
__device__ __forceinline__ void mbar_wait(uint32_t a, uint32_t parity) {
    uint32_t done;
    asm volatile(
        "{ .reg .pred p; "
        "mbarrier.try_wait.parity.acquire.cta.shared::cta.b64 p, [%1], %2; "
        "selp.b32 %0,1,0,p; }"
        : "=r"(done) : "r"(a), "r"(parity) : "memory");
    if (!done) {
        asm volatile(
            "{\n\t.reg .pred P1;\n"
            "WL%=:\n\t"
            "mbarrier.try_wait.parity.acquire.cta.shared::cta.b64 P1, [%0], %1, 0x989680;\n\t"
            "@P1 bra.uni WD%=;\n\t"
            "bra.uni WL%=;\n"
            "WD%=:\n\t}"
            :: "r"(a), "r"(parity) : "memory");
    }
}
__device__ __forceinline__ void ldsm4(uint32_t a, uint32_t* r) {
    asm volatile("ldmatrix.sync.aligned.m8n8.x4.shared.b16 {%0,%1,%2,%3}, [%4];"
                 : "=r"(r[0]), "=r"(r[1]), "=r"(r[2]), "=r"(r[3]) : "r"(a));
}
__device__ __forceinline__ void ldsm4t(uint32_t a, uint32_t* r) {
    asm volatile("ldmatrix.sync.aligned.m8n8.x4.trans.shared.b16 {%0,%1,%2,%3}, [%4];"
                 : "=r"(r[0]), "=r"(r[1]), "=r"(r[2]), "=r"(r[3]) : "r"(a));
}
__device__ __forceinline__ void mma16816(float* c, const uint32_t* a,
                                         uint32_t b0, uint32_t b1) {
    asm volatile("mma.sync.aligned.m16n8k16.row.col.f32.bf16.bf16.f32 "
                 "{%0,%1,%2,%3}, {%4,%5,%6,%7}, {%8,%9}, {%0,%1,%2,%3};"
                 : "+f"(c[0]), "+f"(c[1]), "+f"(c[2]), "+f"(c[3])
                 : "r"(a[0]), "r"(a[1]), "r"(a[2]), "r"(a[3]), "r"(b0), "r"(b1));
}
__device__ __forceinline__ float sigmoidf_(float x) { return 1.0f / (1.0f + expf(-x)); }
__device__ __forceinline__ void split1(float v, __nv_bfloat16& h, __nv_bfloat16& l) {
    h = __float2bfloat16_rn(v);
    l = __float2bfloat16_rn(v - __bfloat162float(h));
}
__device__ __forceinline__ uint32_t swz(uint32_t off) {
    return off ^ ((off >> 3) & 0x70);
}

// ---------------- grid barrier (all 128 blocks resident) ----------------
__device__ __forceinline__ void grid_barrier() {
    __syncthreads();
    if (threadIdx.x == 0) {
        __threadfence();
        unsigned gen = *((volatile unsigned*)&g_bar_gen);
        if (atomicAdd(&g_bar_arrive, 1u) == NBLK - 1) {
            g_bar_arrive = 0;
            __threadfence();
            atomicAdd(&g_bar_gen, 1u);
        } else {
            while (*((volatile unsigned*)&g_bar_gen) == gen) { __nanosleep(20); }
        }
        __threadfence();
    }
    __syncthreads();
}

// ---------------- persistent kernel ----------------
__global__ void __launch_bounds__(NTHR, 1)
lstm_hmma(const float* __restrict__ input,   // [512,64,1024]
          const float* __restrict__ h0,      // [2,64,1024]
          const float* __restrict__ c0,      // [2,64,1024]
          const float* __restrict__ W,       // [2,2048,4096]
          const float* __restrict__ bias,    // [2,4096]
          float* __restrict__ out)
{
    extern __shared__ __align__(1024) char dsm[];
    const uint32_t sbase = smem_u32(dsm);

    __shared__ float s_tr[32][33];
    __shared__ float s_hn[8][64];
    __shared__ __align__(8) unsigned long long s_mbF[NSTG];  // stage full
    __shared__ __align__(8) unsigned long long s_mbE[NSTG];  // stage empty

    const int tid  = threadIdx.x;
    const int wid  = tid >> 5;
    const int lane = tid & 31;
    const int bid  = blockIdx.x;
    const int gid  = bid * NTHR + tid;
    const int lay  = bid >> 6;        // 0: layer0@s, 1: layer1@(s-1)
    const int cg   = bid & 31;        // M tile: rows [cg*128, +128)
    const int ks   = (bid >> 5) & 1;  // K slice: [ks*1024, +1024)
    const int pgrp = bid >> 5;        // partial group: lay*2+ks
    const int m0   = cg * 128;
    const int u0   = bid * 8;         // cell-owned units (both layers)

    const uint32_t mbF = smem_u32(&s_mbF[0]);
    const uint32_t mbE = smem_u32(&s_mbE[0]);
    if (tid == 0) {
#pragma unroll
        for (int i = 0; i < NSTG; i++) {
            mbar_init(mbF + i * 8, NTHR);
            mbar_init(mbE + i * 8, NTHR);
        }
    }
    __syncthreads();

    // warp mapping: kg = k-group (kk pair), wpos -> (mq, nh) m32n32 tile
    const int kg   = wid >> 3;        // 0: kk{0,1}, 1: kk{2,3}
    const int wpos = wid & 7;
    const int mq   = wpos >> 1;       // m offset mq*32
    const int nh   = wpos & 1;        // n offset nh*32

    // ======== phase 0a: x transpose [t][b][u] -> [t][u][b] + bf16 split ====
    for (int tile = bid; tile < SEQ * 64; tile += NBLK) {
        const int t  = tile >> 6;
        const int ut = (tile >> 1) & 31;
        const int bt = tile & 1;
        const int ub = ut * 32, bb = bt * 32;
#pragma unroll
        for (int it = 0; it < 2; it++) {
            int r = (tid >> 5) + it * 16, c = lane;
            s_tr[r][c] = input[((size_t)t * 64 + bb + r) * HID + ub + c];
        }
        __syncthreads();
#pragma unroll
        for (int it = 0; it < 2; it++) {
            int i = (tid >> 5) + it * 16, j = lane;
            __nv_bfloat16 hv, lv;
            split1(s_tr[j][i], hv, lv);
            size_t dst = ((size_t)t * HID + ub + i) * 64 + bb + j;
            g_xhi[dst] = hv;
            g_xlo[dst] = lv;
        }
        __syncthreads();
    }
    // ======== phase 0b: W transpose + gate-permute + split ========
    for (int tile = bid; tile < 2 * 64 * 128; tile += NBLK) {
        const int l  = tile >> 13;
        const int kt = (tile & 8191) >> 7;
        const int nt = tile & 127;
        const int k0 = kt * 32, n0 = nt * 32;
#pragma unroll
        for (int r = 0; r < 2; r++) {
            int kk = (tid >> 5) + r * 16;
            s_tr[kk][lane] = W[((size_t)l * KTOT + k0 + kk) * NOUT + n0 + lane];
        }
        __syncthreads();
#pragma unroll
        for (int r = 0; r < 2; r++) {
            int j = (tid >> 5) + r * 16;
            int n = n0 + j;
            int p = ((n & 1023) << 2) | (n >> 10);
            __nv_bfloat16 hv, lv;
            split1(s_tr[lane][j], hv, lv);
            size_t dst = ((size_t)l * NOUT + p) * KTOT + k0 + lane;
            g_wthi[dst] = hv;
            g_wtlo[dst] = lv;
        }
        __syncthreads();
    }
    // ======== phase 0c: seed h (transposed, split) and c (transposed) =====
    for (int tile = bid; tile < 256; tile += NBLK) {
        const int kind = tile >> 7;
        const int rest = tile & 127;
        const int l  = rest >> 6;
        const int ut = (rest >> 1) & 31;
        const int bt = rest & 1;
        const int ub = ut * 32, bb = bt * 32;
        const float* src = (kind == 0) ? h0 : c0;
#pragma unroll
        for (int it = 0; it < 2; it++) {
            int r = (tid >> 5) + it * 16, c = lane;
            s_tr[r][c] = src[((size_t)l * 64 + bb + r) * HID + ub + c];
        }
        __syncthreads();
#pragma unroll
        for (int it = 0; it < 2; it++) {
            int i = (tid >> 5) + it * 16, j = lane;
            float v = s_tr[j][i];
            if (kind == 0) {
                __nv_bfloat16 hv, lv;
                split1(v, hv, lv);
                size_t dst = (size_t)l * BH + (size_t)(ub + i) * 64 + bb + j;
                g_hhi[dst] = hv;
                g_hlo[dst] = lv;
            } else {
                g_c[(size_t)l * BH + (size_t)(ub + i) * 64 + bb + j] = v;
            }
        }
        __syncthreads();
    }
    grid_barrier();

    // ---- lane-constant ldmatrix row bases + swizzle XORs ----
    const int q  = lane >> 3, r8 = lane & 7;
    const int rowA = mq * 32 + r8 + (q & 1) * 8;
    const uint32_t baseA = (uint32_t)rowA * 128;
    const uint32_t xorA  = (uint32_t)(rowA & 7) * 16;
    const int rowB = (q & 1) * 8 + r8;
    const uint32_t baseB = (uint32_t)rowB * 128;
    const uint32_t xorB  = (uint32_t)(rowB & 7) * 16;
    const uint32_t colq  = (uint32_t)(q >> 1) * 16;

    // ---- hoisted cp.async addressing (lane-constant) ----
    const int irow = tid >> 3;                 // 0..63
    const int ic8  = (tid & 7) * 8;            // element offset within row
    const uint32_t offL0 = swz((uint32_t)irow * 128 + (tid & 7) * 16);
    const uint32_t offL1 = swz((uint32_t)(irow + 64) * 128 + (tid & 7) * 16);

    // W pointers fixed for this CTA (per-thread bases)
    const __nv_bfloat16* WhP0 = g_wthi + ((size_t)lay * NOUT + m0 + irow) * KTOT
                              + ks * KSL + ic8;
    const __nv_bfloat16* WhP1 = WhP0 + (size_t)64 * KTOT;
    const __nv_bfloat16* WoP0 = g_wtlo + ((size_t)lay * NOUT + m0 + irow) * KTOT
                              + ks * KSL + ic8;
    const __nv_bfloat16* WoP1 = WoP0 + (size_t)64 * KTOT;

    // per-thread stage parity bits (producer empty starts at 1 -> first pass)
    unsigned phF = 0u;
    unsigned phE = (1u << NSTG) - 1u;

    // ======== main recurrence: 513 super-steps ========
    for (int s = 0; s <= SEQ; s++) {
        const bool do_l0 = (s < SEQ);
        const bool do_l1 = (s >= 1);
        const bool active = (lay == 0) ? do_l0 : do_l1;

        if (active) {
            // ---- B operand selection (per-thread base pointers) ----
            const __nv_bfloat16 *Bh, *Bl;
            if (lay == 0) {
                if (ks == 0) { Bh = g_xhi + (size_t)s * BH; Bl = g_xlo + (size_t)s * BH; }
                else         { Bh = g_hhi;                  Bl = g_hlo; }
            } else {
                if (ks == 0) { Bh = g_hhi;      Bl = g_hlo; }
                else         { Bh = g_hhi + BH; Bl = g_hlo + BH; }
            }
            const __nv_bfloat16* BhP = Bh + (size_t)tid * 8;
            const __nv_bfloat16* BlP = Bl + (size_t)tid * 8;

            float acc[2][4][4];
#pragma unroll
            for (int i = 0; i < 2; i++)
#pragma unroll
                for (int j = 0; j < 4; j++)
#pragma unroll
                    for (int r = 0; r < 4; r++) acc[i][j][r] = 0.0f;

            // prologue: produce chunks 0,1 into stages 0,1
#pragma unroll
            for (int pc = 0; pc < 2; pc++) {
                mbar_wait(mbE + pc * 8, (phE >> pc) & 1u);
                phE ^= (1u << pc);
                const uint32_t st = sbase + pc * STGB;
                const int kc = pc * CHK;
                cpa16(st + offL0,         WhP0 + kc);
                cpa16(st + 16384 + offL0, WoP0 + kc);
                cpa16(st + offL1,         WhP1 + kc);
                cpa16(st + 16384 + offL1, WoP1 + kc);
                cpa16(st + 32768 + offL0, BhP + kc * 64);
                cpa16(st + 40960 + offL0, BlP + kc * 64);
                cpa_mbar_arrive(mbF + pc * 8);
            }

            for (int ch = 0; ch < NCHK; ch++) {
                const int si = ch % NSTG;
                mbar_wait(mbF + si * 8, (phF >> si) & 1u);
                phF ^= (1u << si);

                // ---- compute chunk ch (this warp's 2 kk of 4) ----
                const uint32_t st = sbase + si * STGB;
#pragma unroll
                for (int kk2 = 0; kk2 < 2; kk2++) {
                    const int kk = kg * 2 + kk2;
                    const uint32_t aoff = (colq + kk * 32) ^ xorA;
                    uint32_t ahi0[4], ahi1[4], alo0[4], alo1[4];
                    ldsm4(st + baseA + aoff, ahi0);
                    ldsm4(st + baseA + 2048 + aoff, ahi1);
                    ldsm4(st + 16384 + baseA + aoff, alo0);
                    ldsm4(st + 16384 + baseA + 2048 + aoff, alo1);
#pragma unroll
                    for (int pl = 0; pl < 2; pl++) {
                        const int p = nh * 2 + pl;
                        const uint32_t boff = baseB + (uint32_t)kk * 2048
                                            + ((colq + p * 32) ^ xorB);
                        uint32_t bh[4], bl[4];
                        ldsm4t(st + 32768 + boff, bh);
                        ldsm4t(st + 40960 + boff, bl);
                        mma16816(acc[0][2 * pl],     ahi0, bh[0], bh[1]);
                        mma16816(acc[0][2 * pl],     ahi0, bl[0], bl[1]);
                        mma16816(acc[0][2 * pl],     alo0, bh[0], bh[1]);
                        mma16816(acc[0][2 * pl + 1], ahi0, bh[2], bh[3]);
                        mma16816(acc[0][2 * pl + 1], ahi0, bl[2], bl[3]);
                        mma16816(acc[0][2 * pl + 1], alo0, bh[2], bh[3]);
                        mma16816(acc[1][2 * pl],     ahi1, bh[0], bh[1]);
                        mma16816(acc[1][2 * pl],     ahi1, bl[0], bl[1]);
                        mma16816(acc[1][2 * pl],     alo1, bh[0], bh[1]);
                        mma16816(acc[1][2 * pl + 1], ahi1, bh[2], bh[3]);
                        mma16816(acc[1][2 * pl + 1], ahi1, bl[2], bl[3]);
                        mma16816(acc[1][2 * pl + 1], alo1, bh[2], bh[3]);
                    }
                }
                mbar_arrive(mbE + si * 8);

                // ---- produce chunk ch+2 into stage (ch+2)%3 ----
                if (ch + 2 < NCHK) {
                    const int s2 = (ch + 2) % NSTG;
                    mbar_wait(mbE + s2 * 8, (phE >> s2) & 1u);
                    phE ^= (1u << s2);
                    const uint32_t st2 = sbase + s2 * STGB;
                    const int kc = (ch + 2) * CHK;
                    cpa16(st2 + offL0,         WhP0 + kc);
                    cpa16(st2 + 16384 + offL0, WoP0 + kc);
                    cpa16(st2 + offL1,         WhP1 + kc);
                    cpa16(st2 + 16384 + offL1, WoP1 + kc);
                    cpa16(st2 + 32768 + offL0, BhP + kc * 64);
                    cpa16(st2 + 40960 + offL0, BlP + kc * 64);
                    cpa_mbar_arrive(mbF + s2 * 8);
                }
            }
            __syncthreads();   // all computes done; stage smem reusable

            // ---- k-group reduction via (reused) stage-0 smem ----
            if (kg == 1) {
                const uint32_t rb = sbase + (uint32_t)wpos * 4096 + (uint32_t)lane * 4;
#pragma unroll
                for (int i = 0; i < 2; i++)
#pragma unroll
                    for (int j = 0; j < 4; j++)
#pragma unroll
                        for (int r = 0; r < 4; r++) {
                            asm volatile("st.shared.b32 [%0], %1;"
                                :: "r"(rb + ((i * 4 + j) * 4 + r) * 128),
                                   "f"(acc[i][j][r]) : "memory");
                        }
            }
            __syncthreads();

            if (kg == 0) {
                const uint32_t rb = sbase + (uint32_t)wpos * 4096 + (uint32_t)lane * 4;
                const int g4 = lane >> 2;
                const int tt = lane & 3;
#pragma unroll
                for (int i = 0; i < 2; i++) {
#pragma unroll
                    for (int j = 0; j < 4; j++) {
                        float o[4];
#pragma unroll
                        for (int r = 0; r < 4; r++) {
                            float v;
                            asm volatile("ld.shared.b32 %0, [%1];"
                                : "=f"(v)
                                : "r"(rb + ((i * 4 + j) * 4 + r) * 128));
                            o[r] = acc[i][j][r] + v;
                        }
                        const int prow = m0 + mq * 32 + i * 16 + g4;
                        const int col  = nh * 32 + j * 8 + 2 * tt;
                        float* pp = g_partial + ((size_t)pgrp * NOUT + prow) * 64 + col;
                        *reinterpret_cast<float2*>(pp) = make_float2(o[0], o[1]);
                        *reinterpret_cast<float2*>(pp + 8 * 64) = make_float2(o[2], o[3]);
                    }
                }
            }
        }
        grid_barrier();

        // ---- cell phase: both layers, 8 units x 64 batches per CTA ----
        {
            const int b  = tid & 63;
            const int ul = tid >> 6;            // 0..7
            const int u  = u0 + ul;
#pragma unroll
            for (int cl = 0; cl < 2; cl++) {
                if (cl == 0 ? !do_l0 : !do_l1) continue;
                float gv[4];
#pragma unroll
                for (int gate = 0; gate < 4; gate++) {
                    const int p = 4 * u + gate;
                    float sum = bias[(size_t)cl * NOUT + gate * 1024 + u];
                    sum += g_partial[((size_t)(cl * 2 + 0) * NOUT + p) * 64 + b];
                    sum += g_partial[((size_t)(cl * 2 + 1) * NOUT + p) * 64 + b];
                    gv[gate] = sum;
                }
                const size_t cidx = (size_t)cl * BH + (size_t)u * 64 + b;
                const float gi = sigmoidf_(gv[0]);
                const float gj = tanhf(gv[1]);
                const float gf = sigmoidf_(gv[2]);
                const float go = sigmoidf_(gv[3]);
                const float cn = g_c[cidx] * gf + gi * gj;
                g_c[cidx] = cn;
                const float hn = tanhf(cn) * go;
                g_hf[cidx] = hn;
                __nv_bfloat16 hv, lv;
                split1(hn, hv, lv);
                g_hhi[cidx] = hv;
                g_hlo[cidx] = lv;
                if (cl == 1) s_hn[ul][b] = hn;
            }
            __syncthreads();
            if (do_l1 && tid < 64) {
                const int b2 = tid;
                float* op = out + (size_t)(s - 1) * BH + (size_t)b2 * HID + u0;
                reinterpret_cast<float4*>(op)[0] =
                    make_float4(s_hn[0][b2], s_hn[1][b2], s_hn[2][b2], s_hn[3][b2]);
                reinterpret_cast<float4*>(op)[1] =
                    make_float4(s_hn[4][b2], s_hn[5][b2], s_hn[6][b2], s_hn[7][b2]);
            }
        }
        grid_barrier();
    }

    // ======== tail: last_hidden + last_cell, de-transpose ========
    for (int i = gid; i < 2 * BH; i += GTH) {
        int l = i >> 16, rr = i & 65535, b = rr >> 10, u = rr & 1023;
        out[(size_t)SEQ * BH + i] = g_hf[(size_t)l * BH + (size_t)u * 64 + b];
        out[(size_t)SEQ * BH + 2 * BH + i] = g_c[(size_t)l * BH + (size_t)u * 64 + b];
    }
}

// ---------------- launch: ONE graph node ----------------
extern "C" void kernel_launch(void* const* d_in, const int* in_sizes, int n_in,
                              void* d_out, int out_size) {
    const float* input = (const float*)d_in[0];
    const float* h0    = (const float*)d_in[1];
    const float* c0    = (const float*)d_in[2];
    const float* W     = (const float*)d_in[3];
    const float* bias  = (const float*)d_in[4];
    float* out = (float*)d_out;

    cudaFuncSetAttribute(lstm_hmma, cudaFuncAttributeMaxDynamicSharedMemorySize, DSMEM);
    lstm_hmma<<<NBLK, NTHR, DSMEM>>>(input, h0, c0, W, bias, out);
}